// round 16
// baseline (speedup 1.0000x reference)
#include <cuda_runtime.h>
#include <cuda_bf16.h>
#include <cuda_fp16.h>
#include <cstdint>

#define NUSR 100000
#define NITM 50000
#define NNODE (NUSR + NITM)
#define DD 128
#define EE 1500000
#define HALFD 64
#define KCAT 320
#define NBLK 586     // ceil(NNODE/256)
#define UBLKS 782    // ceil(NUSR/128)
#define IBLKS 391    // ceil(NITM/128)
#define PROJ_BLKS (UBLKS + IBLKS)
#define EMB_BLKS 18750   // ceil(NNODE*32/256)
#define EDGE_BLKS 5860   // ceil(EE/256)

// fp16 weight buffer offsets (halves), transposed [n][K] per matrix
#define OFF_U  0
#define OFF_I  40960
#define OFF_W0 81920
#define OFF_W1 114688
#define OFF_V0 147456
#define OFF_V1 163840
#define WTOT   180224

// smem stride (halves) — 32 data + 8 pad, conflict-free for ldmatrix phases
#define PSTR 40

// -------- scratch (device globals: allocation-free) --------
__device__ __half g_cat16[(size_t)NNODE * KCAT];
__device__ __half g_x16  [(size_t)NNODE * DD];
__device__ __half g_agg16[(size_t)NNODE * DD];
__device__ __half g_wth  [WTOT];
__device__ int    g_deg[NNODE];
__device__ int    g_bsum[1024];
__device__ int    g_offs[NNODE + 1];
__device__ int    g_cursor[NNODE];
__device__ int    g_csr[EE];
__device__ __nv_bfloat16 g_ufeb[5000 * 128];
__device__ __nv_bfloat16 g_ifeb[8000 * 128];
__device__ __nv_bfloat16 g_web [30000 * 64];

// -------- fp16 mma helper: m16n8k16, fp32 accumulate --------
__device__ __forceinline__ void mma_f16(float* c, const uint32_t* a, const uint32_t* b) {
    asm volatile(
        "mma.sync.aligned.m16n8k16.row.col.f32.f16.f16.f32 "
        "{%0,%1,%2,%3}, {%4,%5,%6,%7}, {%8,%9}, {%0,%1,%2,%3};"
        : "+f"(c[0]), "+f"(c[1]), "+f"(c[2]), "+f"(c[3])
        : "r"(a[0]), "r"(a[1]), "r"(a[2]), "r"(a[3]), "r"(b[0]), "r"(b[1]));
}

__device__ __forceinline__ void ldsm4(uint32_t* r, uint32_t addr) {
    asm volatile("ldmatrix.sync.aligned.m8n8.x4.shared.b16 {%0,%1,%2,%3}, [%4];"
                 : "=r"(r[0]), "=r"(r[1]), "=r"(r[2]), "=r"(r[3]) : "r"(addr));
}

__device__ __forceinline__ void cp16(void* smem_dst, const void* gsrc, bool pred) {
    uint32_t dst = (uint32_t)__cvta_generic_to_shared(smem_dst);
    int sz = pred ? 16 : 0;
    asm volatile("cp.async.ca.shared.global [%0], [%1], 16, %2;\n"
                 :: "r"(dst), "l"(gsrc), "r"(sz));
}
__device__ __forceinline__ void cp_commit() { asm volatile("cp.async.commit_group;\n"); }
__device__ __forceinline__ void cp_wait0()  { asm volatile("cp.async.wait_group 0;\n"); }
__device__ __forceinline__ void cp_wait1()  { asm volatile("cp.async.wait_group 1;\n"); }
__device__ __forceinline__ void cp_wait2()  { asm volatile("cp.async.wait_group 2;\n"); }
__device__ __forceinline__ void cp_wait3()  { asm volatile("cp.async.wait_group 3;\n"); }

// ======== prep: tables->bf16, weights->fp16 transposed [n][K], zero deg ========
__global__ void prep_kernel(const float* __restrict__ ufe, const float* __restrict__ ife,
                            const float* __restrict__ we,
                            const float* __restrict__ uW, const float* __restrict__ iW,
                            const float* __restrict__ w0, const float* __restrict__ w1,
                            const float* __restrict__ v0, const float* __restrict__ v1) {
    int i0 = blockIdx.x * blockDim.x + threadIdx.x;
    int st = gridDim.x * blockDim.x;
    for (int i = i0; i < 3584000; i += st) {
        if      (i < 640000)  g_ufeb[i]           = __float2bfloat16(ufe[i]);
        else if (i < 1664000) g_ifeb[i - 640000]  = __float2bfloat16(ife[i - 640000]);
        else                  g_web [i - 1664000] = __float2bfloat16(we [i - 1664000]);
    }
    for (int i = i0; i < WTOT; i += st) {
        const float* src; int loc, dbase, K;
        if      (i < OFF_I)  { src = uW; loc = i - OFF_U;  dbase = OFF_U;  K = 320; }
        else if (i < OFF_W0) { src = iW; loc = i - OFF_I;  dbase = OFF_I;  K = 320; }
        else if (i < OFF_W1) { src = w0; loc = i - OFF_W0; dbase = OFF_W0; K = 256; }
        else if (i < OFF_V0) { src = w1; loc = i - OFF_W1; dbase = OFF_W1; K = 256; }
        else if (i < OFF_V1) { src = v0; loc = i - OFF_V0; dbase = OFF_V0; K = 128; }
        else                 { src = v1; loc = i - OFF_V1; dbase = OFF_V1; K = 128; }
        int k = loc >> 7, n = loc & 127;
        g_wth[dbase + n * K + k] = __float2half(src[loc]);
    }
    for (int i = i0; i < NNODE; i += st) g_deg[i] = 0;
}

// ======== embed (fp16 output) + degree count ========
__global__ void embed_deg_kernel(const int* __restrict__ uf,  const int* __restrict__ itf,
                                 const int* __restrict__ ut,  const int* __restrict__ it,
                                 const int* __restrict__ dstp) {
    if (blockIdx.x >= EMB_BLKS) {
        int i = (blockIdx.x - EMB_BLKS) * blockDim.x + threadIdx.x;
        if (i < EE) atomicAdd(&g_deg[dstp[i]], 1);
        return;
    }
    int gw   = (blockIdx.x * blockDim.x + threadIdx.x) >> 5;
    int lane = threadIdx.x & 31;
    if (gw >= NNODE) return;
    int n = gw;
    bool user = n < NUSR;
    const int* f = user ? uf + (size_t)n * 10 : itf + (size_t)(n - NUSR) * 10;
    const __nv_bfloat16* tab = user ? g_ufeb : g_ifeb;

    float4 a = make_float4(0.f, 0.f, 0.f, 0.f);
#pragma unroll
    for (int j = 0; j < 10; j++) {
        int r = __ldg(f + j);
        uint2 v = __ldg((const uint2*)(tab + (size_t)r * DD) + lane);
        float2 p0 = __bfloat1622float2(*(__nv_bfloat162*)&v.x);
        float2 p1 = __bfloat1622float2(*(__nv_bfloat162*)&v.y);
        a.x += p0.x; a.y += p0.y; a.z += p1.x; a.w += p1.y;
    }
    __half* catrow = g_cat16 + (size_t)n * KCAT;
    __half2 h01 = __floats2half2_rn(a.x * 0.1f, a.y * 0.1f);
    __half2 h23 = __floats2half2_rn(a.z * 0.1f, a.w * 0.1f);
    uint2 pk;
    pk.x = *(uint32_t*)&h01; pk.y = *(uint32_t*)&h23;
    ((uint2*)catrow)[lane] = pk;

    const int* t = user ? ut + (size_t)n * 24 : it + (size_t)(n - NUSR) * 24;
#pragma unroll
    for (int fl = 0; fl < 3; fl++) {
        float2 b = make_float2(0.f, 0.f);
#pragma unroll
        for (int w = 0; w < 8; w++) {
            int r = __ldg(t + fl * 8 + w);
            uint32_t v = __ldg((const uint32_t*)(g_web + (size_t)r * HALFD) + lane);
            float2 p = __bfloat1622float2(*(__nv_bfloat162*)&v);
            b.x += p.x; b.y += p.y;
        }
        __half2 hb = __floats2half2_rn(b.x * 0.125f, b.y * 0.125f);
        *(uint32_t*)(catrow + 128 + fl * 64 + lane * 2) = *(uint32_t*)&hb;
    }
}

// -------- scans --------
__global__ void scan1_kernel() {
    __shared__ int sm[256];
    int tid = threadIdx.x;
    int i = blockIdx.x * 256 + tid;
    int v = (i < NNODE) ? g_deg[i] : 0;
    sm[tid] = v;
    __syncthreads();
#pragma unroll
    for (int d = 1; d < 256; d <<= 1) {
        int t = (tid >= d) ? sm[tid - d] : 0;
        __syncthreads();
        sm[tid] += t;
        __syncthreads();
    }
    if (i < NNODE) g_offs[i] = sm[tid] - v;
    if (tid == 255) g_bsum[blockIdx.x] = sm[255];
}

__global__ void scan2_kernel() {
    __shared__ int sm[1024];
    int tid = threadIdx.x;
    int v = (tid < NBLK) ? g_bsum[tid] : 0;
    sm[tid] = v;
    __syncthreads();
#pragma unroll
    for (int d = 1; d < 1024; d <<= 1) {
        int t = (tid >= d) ? sm[tid - d] : 0;
        __syncthreads();
        sm[tid] += t;
        __syncthreads();
    }
    g_bsum[tid] = sm[tid] - v;
}

__global__ void scan3_kernel() {
    int i = blockIdx.x * blockDim.x + threadIdx.x;
    if (i < NNODE) {
        int o = g_offs[i] + g_bsum[i >> 8];
        g_offs[i] = o;
        g_cursor[i] = o;
    }
    if (i == 0) g_offs[NNODE] = EE;
}

// -------- gather aggregation fp16, 4-way unrolled (warp per node) --------
__global__ void agg_kernel() {
    int gw   = (blockIdx.x * blockDim.x + threadIdx.x) >> 5;
    int lane = threadIdx.x & 31;
    if (gw >= NNODE) return;
    int off = g_offs[gw];
    int end = g_offs[gw + 1];
    float4 acc = make_float4(0.f, 0.f, 0.f, 0.f);
    int j = off;
    for (; j + 4 <= end; j += 4) {
        int s0 = __ldg(&g_csr[j]);
        int s1 = __ldg(&g_csr[j + 1]);
        int s2 = __ldg(&g_csr[j + 2]);
        int s3 = __ldg(&g_csr[j + 3]);
        uint2 v0 = __ldg((const uint2*)(g_x16 + (size_t)s0 * DD) + lane);
        uint2 v1 = __ldg((const uint2*)(g_x16 + (size_t)s1 * DD) + lane);
        uint2 v2 = __ldg((const uint2*)(g_x16 + (size_t)s2 * DD) + lane);
        uint2 v3 = __ldg((const uint2*)(g_x16 + (size_t)s3 * DD) + lane);
#pragma unroll
        for (int q = 0; q < 4; q++) {
            uint2 v = (q == 0) ? v0 : (q == 1) ? v1 : (q == 2) ? v2 : v3;
            float2 p0 = __half22float2(*(__half2*)&v.x);
            float2 p1 = __half22float2(*(__half2*)&v.y);
            acc.x += p0.x; acc.y += p0.y; acc.z += p1.x; acc.w += p1.y;
        }
    }
    for (; j < end; j++) {
        int s = __ldg(&g_csr[j]);
        uint2 v = __ldg((const uint2*)(g_x16 + (size_t)s * DD) + lane);
        float2 p0 = __half22float2(*(__half2*)&v.x);
        float2 p1 = __half22float2(*(__half2*)&v.y);
        acc.x += p0.x; acc.y += p0.y; acc.z += p1.x; acc.w += p1.y;
    }
    float sc = 1.0f / fmaxf((float)(end - off), 1.0f);
    __half2 p0 = __floats2half2_rn(acc.x * sc, acc.y * sc);
    __half2 p1 = __floats2half2_rn(acc.z * sc, acc.w * sc);
    uint2 pk;
    pk.x = *(uint32_t*)&p0; pk.y = *(uint32_t*)&p1;
    ((uint2*)(g_agg16 + (size_t)gw * DD))[lane] = pk;
}

// ======== fp16 projection GEMM (blocks [0,PROJ_BLKS)) + CSR fill (beyond) ========
__global__ __launch_bounds__(256) void proj_fill(
    const float* __restrict__ ubias, const float* __restrict__ ibias,
    const float* __restrict__ uid,   const float* __restrict__ iid,
    const int* __restrict__ srcp, const int* __restrict__ dstp)
{
    if (blockIdx.x >= PROJ_BLKS) {
        int i = (blockIdx.x - PROJ_BLKS) * blockDim.x + threadIdx.x;
        if (i < EE) {
            int d = dstp[i];
            int pos = atomicAdd(&g_cursor[d], 1);
            g_csr[pos] = srcp[i];
        }
        return;
    }

    extern __shared__ __half smh[];
    __half* As = smh;                       // 3*128*PSTR
    __half* Ws = smh + 3 * 128 * PSTR;      // 2*128*PSTR

    bool user = blockIdx.x < UBLKS;
    const __half* A      = user ? g_cat16 : g_cat16 + (size_t)NUSR * KCAT;
    const __half* Wt     = g_wth + (user ? OFF_U : OFF_I);
    const float* bias    = user ? ubias : ibias;
    const float* addmat  = user ? uid : iid;
    __half* out          = user ? g_x16 : g_x16 + (size_t)NUSR * DD;
    int M                = user ? NUSR : NITM;
    int r0               = (user ? blockIdx.x : blockIdx.x - UBLKS) * 128;

    int tid  = threadIdx.x;
    int lane = tid & 31;
    int wid  = tid >> 5;
    int wm = wid & 1, wn = wid >> 1;
    int g  = lane >> 2, tg = lane & 3;
    int lrow = (lane & 7) + ((lane & 8) ? 8 : 0);
    int lka  = (lane & 16) ? 8 : 0;
    int lnc  = (lane & 7) + ((lane & 16) ? 8 : 0);
    int lkb  = (lane & 8) ? 8 : 0;

    uint32_t as_sm = (uint32_t)__cvta_generic_to_shared(As);
    uint32_t ws_sm = (uint32_t)__cvta_generic_to_shared(Ws);

    float acc[4][4][4];
#pragma unroll
    for (int mt = 0; mt < 4; mt++)
#pragma unroll
        for (int nt = 0; nt < 4; nt++)
#pragma unroll
            for (int u = 0; u < 4; u++) acc[mt][nt][u] = 0.f;

    const int T = KCAT / 32;
    auto issueA = [&](int t, int s) {
#pragma unroll
        for (int l = 0; l < 2; l++) {
            int idx = tid + l * 256;
            int m = idx >> 2, c4 = idx & 3;
            int row = r0 + m;
            cp16(As + (size_t)s * 128 * PSTR + m * PSTR + c4 * 8,
                 A + (size_t)row * KCAT + t * 32 + c4 * 8, row < M);
        }
        cp_commit();
    };
    auto issueW = [&](int t, int s) {
#pragma unroll
        for (int l = 0; l < 2; l++) {
            int idx = tid + l * 256;
            int n = idx >> 2, c4 = idx & 3;
            cp16(Ws + (size_t)s * 128 * PSTR + n * PSTR + c4 * 8,
                 Wt + (size_t)n * KCAT + t * 32 + c4 * 8, true);
        }
        cp_commit();
    };

    issueW(0, 0);
    issueA(0, 0);
    issueA(1, 1);
    for (int t = 0; t < T; t++) {
        int sa = t % 3, sw = t & 1;
        if (t + 1 < T) issueW(t + 1, (t + 1) & 1);
        if (t + 2 < T) issueA(t + 2, (t + 2) % 3);
        if (t + 2 < T) cp_wait3();
        else if (t + 1 < T) cp_wait2();
        else cp_wait0();
        __syncthreads();
        uint32_t sab = as_sm + (uint32_t)sa * 128 * PSTR * 2;
        uint32_t swb = ws_sm + (uint32_t)sw * 128 * PSTR * 2;
#pragma unroll
        for (int kk = 0; kk < 32; kk += 16) {
            uint32_t afr[4][4];
#pragma unroll
            for (int mt = 0; mt < 4; mt++) {
                int rb0 = wm * 64 + mt * 16;
                ldsm4(afr[mt], sab + ((rb0 + lrow) * PSTR + kk + lka) * 2);
            }
            uint32_t bfr[4][2];
#pragma unroll
            for (int np = 0; np < 2; np++) {
                uint32_t r4[4];
                int nb0 = wn * 32 + np * 16;
                ldsm4(r4, swb + ((nb0 + lnc) * PSTR + kk + lkb) * 2);
                bfr[np * 2][0] = r4[0]; bfr[np * 2][1] = r4[1];
                bfr[np * 2 + 1][0] = r4[2]; bfr[np * 2 + 1][1] = r4[3];
            }
#pragma unroll
            for (int mt = 0; mt < 4; mt++)
#pragma unroll
                for (int nt = 0; nt < 4; nt++)
                    mma_f16(acc[mt][nt], afr[mt], bfr[nt]);
        }
        __syncthreads();
    }

#pragma unroll
    for (int mt = 0; mt < 4; mt++) {
#pragma unroll
        for (int nt = 0; nt < 4; nt++) {
            int col = wn * 32 + nt * 8 + tg * 2;
            int rowa = r0 + wm * 64 + mt * 16 + g;
            int rowb = rowa + 8;
            float b0 = bias[col], b1 = bias[col + 1];
            if (rowa < M) {
                float x0 = acc[mt][nt][0] + b0 + addmat[(size_t)rowa * 128 + col];
                float x1 = acc[mt][nt][1] + b1 + addmat[(size_t)rowa * 128 + col + 1];
                *(__half2*)(out + (size_t)rowa * 128 + col) = __floats2half2_rn(x0, x1);
            }
            if (rowb < M) {
                float x2 = acc[mt][nt][2] + b0 + addmat[(size_t)rowb * 128 + col];
                float x3 = acc[mt][nt][3] + b1 + addmat[(size_t)rowb * 128 + col + 1];
                *(__half2*)(out + (size_t)rowb * 128 + col) = __floats2half2_rn(x2, x3);
            }
        }
    }
}

// ======== fused SAGE layer fp16: BK=32, 12 iterations, ldmatrix fragments ========
// t 0..3: agg16 @ vW^T -> h;  t 4..7: x16 @ wW^T[0:128];  t 8..11: Hs @ wW^T[128:256]
// dyn smem (halves): As[3][128][PSTR] | Ws[2][128][PSTR] | Hs[128][128] (word-XOR swizzle)
template <bool RELU, bool OUT16>
__global__ __launch_bounds__(256) void sage_layer(
    int voff, const float* __restrict__ vb,
    int woff, const float* __restrict__ wb,
    float* __restrict__ outf, int M)
{
    extern __shared__ __half smh[];
    __half*  As = smh;                           // 3*128*PSTR
    __half*  Ws = smh + 3 * 128 * PSTR;          // 2*128*PSTR
    __half2* H2 = (__half2*)(smh + 3 * 128 * PSTR + 2 * 128 * PSTR);
    const __half* vW = g_wth + voff;   // [n][128]
    const __half* wW = g_wth + woff;   // [n][256]

    int tid  = threadIdx.x;
    int lane = tid & 31;
    int wid  = tid >> 5;
    int wm = wid & 1, wn = wid >> 1;
    int g  = lane >> 2, tg = lane & 3;
    int lrow = (lane & 7) + ((lane & 8) ? 8 : 0);
    int lka  = (lane & 16) ? 8 : 0;
    int lnc  = (lane & 7) + ((lane & 16) ? 8 : 0);
    int lkb  = (lane & 8) ? 8 : 0;
    int r0 = blockIdx.x * 128;

    uint32_t as_sm = (uint32_t)__cvta_generic_to_shared(As);
    uint32_t ws_sm = (uint32_t)__cvta_generic_to_shared(Ws);
    uint32_t h2_sm = (uint32_t)__cvta_generic_to_shared(H2);

    float acc[4][4][4];
#pragma unroll
    for (int mt = 0; mt < 4; mt++)
#pragma unroll
        for (int nt = 0; nt < 4; nt++)
#pragma unroll
            for (int u = 0; u < 4; u++) acc[mt][nt][u] = 0.f;

    auto issueA = [&](int at, int s) {
        const __half* Ap = (at < 4) ? g_agg16 : g_x16;
        int kt = (at < 4) ? at : at - 4;
#pragma unroll
        for (int l = 0; l < 2; l++) {
            int idx = tid + l * 256;
            int m = idx >> 2, c4 = idx & 3;
            int row = r0 + m;
            cp16(As + (size_t)s * 128 * PSTR + m * PSTR + c4 * 8,
                 Ap + (size_t)row * DD + kt * 32 + c4 * 8, row < M);
        }
        cp_commit();
    };
    auto issueW = [&](int wt, int s) {
#pragma unroll
        for (int l = 0; l < 2; l++) {
            int idx = tid + l * 256;
            int n = idx >> 2, c4 = idx & 3;
            const __half* src = (wt < 4) ? (vW + (size_t)n * 128 + wt * 32)
                                         : (wW + (size_t)n * 256 + (wt - 4) * 32);
            cp16(Ws + (size_t)s * 128 * PSTR + n * PSTR + c4 * 8, src + c4 * 8, true);
        }
        cp_commit();
    };

    issueW(0, 0);
    issueA(0, 0);
    issueA(1, 1);

    for (int t = 0; t < 12; t++) {
        int sa = t % 3, sw = t & 1;
        if (t + 1 < 12) issueW(t + 1, (t + 1) & 1);
        if (t + 2 < 8)  issueA(t + 2, (t + 2) % 3);
        if (t <= 5) cp_wait3();
        else if (t == 6) cp_wait2();
        else if (t < 11) cp_wait1();
        else cp_wait0();
        __syncthreads();

        uint32_t sab = as_sm + (uint32_t)sa * 128 * PSTR * 2;
        uint32_t swb = ws_sm + (uint32_t)sw * 128 * PSTR * 2;
#pragma unroll
        for (int kk = 0; kk < 32; kk += 16) {
            uint32_t afr[4][4];
#pragma unroll
            for (int mt = 0; mt < 4; mt++) {
                int rb0 = wm * 64 + mt * 16;
                if (t < 8) {
                    ldsm4(afr[mt], sab + ((rb0 + lrow) * PSTR + kk + lka) * 2);
                } else {
                    int row = rb0 + lrow;
                    int xr = (row & 7) << 2;
                    int word = ((t - 8) * 16 + (kk >> 1) + (lka >> 1)) ^ xr;
                    ldsm4(afr[mt], h2_sm + (row * 64 + word) * 4);
                }
            }
            uint32_t bfr[4][2];
#pragma unroll
            for (int np = 0; np < 2; np++) {
                uint32_t r4[4];
                int nb0 = wn * 32 + np * 16;
                ldsm4(r4, swb + ((nb0 + lnc) * PSTR + kk + lkb) * 2);
                bfr[np * 2][0] = r4[0]; bfr[np * 2][1] = r4[1];
                bfr[np * 2 + 1][0] = r4[2]; bfr[np * 2 + 1][1] = r4[3];
            }
#pragma unroll
            for (int mt = 0; mt < 4; mt++)
#pragma unroll
                for (int nt = 0; nt < 4; nt++)
                    mma_f16(acc[mt][nt], afr[mt], bfr[nt]);
        }

        if (t == 3) {
            // h = relu(acc + vb) -> Hs (fp16, swizzled), reset acc
#pragma unroll
            for (int mt = 0; mt < 4; mt++) {
#pragma unroll
                for (int nt = 0; nt < 4; nt++) {
                    int col = wn * 32 + nt * 8 + tg * 2;
                    int ra = wm * 64 + mt * 16 + g;
                    int cp = col >> 1;
                    float b0 = vb[col], b1 = vb[col + 1];
                    int xra = (ra & 7) << 2;
                    H2[ra * 64 + (cp ^ xra)] =
                        __floats2half2_rn(fmaxf(acc[mt][nt][0] + b0, 0.f),
                                          fmaxf(acc[mt][nt][1] + b1, 0.f));
                    int xrb = ((ra + 8) & 7) << 2;
                    H2[(ra + 8) * 64 + (cp ^ xrb)] =
                        __floats2half2_rn(fmaxf(acc[mt][nt][2] + b0, 0.f),
                                          fmaxf(acc[mt][nt][3] + b1, 0.f));
#pragma unroll
                    for (int u = 0; u < 4; u++) acc[mt][nt][u] = 0.f;
                }
            }
        }
        __syncthreads();
    }

    // epilogue
#pragma unroll
    for (int mt = 0; mt < 4; mt++) {
#pragma unroll
        for (int nt = 0; nt < 4; nt++) {
            int col = wn * 32 + nt * 8 + tg * 2;
            int rowa = r0 + wm * 64 + mt * 16 + g;
            int rowb = rowa + 8;
            float b0 = wb[col], b1 = wb[col + 1];
            float x0 = acc[mt][nt][0] + b0, x1 = acc[mt][nt][1] + b1;
            float x2 = acc[mt][nt][2] + b0, x3 = acc[mt][nt][3] + b1;
            if (RELU) {
                x0 = fmaxf(x0, 0.f); x1 = fmaxf(x1, 0.f);
                x2 = fmaxf(x2, 0.f); x3 = fmaxf(x3, 0.f);
            }
            if (OUT16) {
                if (rowa < M)
                    *(__half2*)(g_x16 + (size_t)rowa * 128 + col) = __floats2half2_rn(x0, x1);
                if (rowb < M)
                    *(__half2*)(g_x16 + (size_t)rowb * 128 + col) = __floats2half2_rn(x2, x3);
            } else {
                if (rowa < M)
                    *(float2*)(outf + (size_t)rowa * 128 + col) = make_float2(x0, x1);
                if (rowb < M)
                    *(float2*)(outf + (size_t)rowb * 128 + col) = make_float2(x2, x3);
            }
        }
    }
}

// -------- launch --------
extern "C" void kernel_launch(void* const* d_in, const int* in_sizes, int n_in,
                              void* d_out, int out_size) {
    const int*   edge          = (const int*)d_in[0];
    const int*   src           = edge;
    const int*   dstp          = edge + EE;
    const int*   user_features = (const int*)d_in[1];
    const int*   item_features = (const int*)d_in[2];
    const int*   user_text     = (const int*)d_in[3];
    const int*   item_text     = (const int*)d_in[4];
    const float* user_id_emb   = (const float*)d_in[5];
    const float* item_id_emb   = (const float*)d_in[6];
    const float* user_feat_emb = (const float*)d_in[7];
    const float* item_feat_emb = (const float*)d_in[8];
    const float* word_emb      = (const float*)d_in[9];
    const float* user_projW    = (const float*)d_in[10];
    const float* user_projb    = (const float*)d_in[11];
    const float* item_projW    = (const float*)d_in[12];
    const float* item_projb    = (const float*)d_in[13];
    const float* w0W = (const float*)d_in[14];
    const float* w0b = (const float*)d_in[15];
    const float* w1W = (const float*)d_in[16];
    const float* w1b = (const float*)d_in[17];
    const float* v0W = (const float*)d_in[18];
    const float* v0b = (const float*)d_in[19];
    const float* v1W = (const float*)d_in[20];
    const float* v1b = (const float*)d_in[21];

    const int PROJ_SMEM = (3 * 128 * PSTR + 2 * 128 * PSTR) * 2;                 // 51200
    const int SAGE_SMEM = (3 * 128 * PSTR + 2 * 128 * PSTR) * 2 + 128 * 128 * 2; // 83968
    cudaFuncSetAttribute(proj_fill, cudaFuncAttributeMaxDynamicSharedMemorySize, PROJ_SMEM);
    cudaFuncSetAttribute(sage_layer<true, true>,   cudaFuncAttributeMaxDynamicSharedMemorySize, SAGE_SMEM);
    cudaFuncSetAttribute(sage_layer<false, false>, cudaFuncAttributeMaxDynamicSharedMemorySize, SAGE_SMEM);

    // 0: tables->bf16, weights->fp16^T, zero deg
    prep_kernel<<<2048, 256>>>(user_feat_emb, item_feat_emb, word_emb,
                               user_projW, item_projW, w0W, w1W, v0W, v1W);
    // 1: embed fp16 (+ deg counting riding along)
    embed_deg_kernel<<<EMB_BLKS + EDGE_BLKS, 256>>>(
        user_features, item_features, user_text, item_text, dstp);
    // 2-4: exclusive scan of degrees
    scan1_kernel<<<NBLK, 256>>>();
    scan2_kernel<<<1, 1024>>>();
    scan3_kernel<<<(NNODE + 255) / 256, 256>>>();
    // 5: fp16 projection GEMM (+ CSR fill riding along) -> g_x16
    proj_fill<<<PROJ_BLKS + EDGE_BLKS, 256, PROJ_SMEM>>>(
        user_projb, item_projb, user_id_emb, item_id_emb, src, dstp);

    // ----- layer 0 -----
    agg_kernel<<<(NNODE * 32 + 255) / 256, 256>>>();
    sage_layer<true, true><<<(NNODE + 127) / 128, 256, SAGE_SMEM>>>(
        OFF_V0, v0b, OFF_W0, w0b, nullptr, NNODE);

    // ----- layer 1 -----
    agg_kernel<<<(NNODE * 32 + 255) / 256, 256>>>();
    sage_layer<false, false><<<(NNODE + 127) / 128, 256, SAGE_SMEM>>>(
        OFF_V1, v1b, OFF_W1, w1b, (float*)d_out, NNODE);
}

// round 17
// speedup vs baseline: 1.3646x; 1.3646x over previous
#include <cuda_runtime.h>
#include <cuda_bf16.h>
#include <cuda_fp16.h>
#include <cstdint>

#define NUSR 100000
#define NITM 50000
#define NNODE (NUSR + NITM)
#define DD 128
#define EE 1500000
#define HALFD 64
#define KCAT 320
#define NBLK 586     // ceil(NNODE/256)
#define UBLKS 782    // ceil(NUSR/128)
#define IBLKS 391    // ceil(NITM/128)
#define PROJ_BLKS (UBLKS + IBLKS)
#define EMB_BLKS 18750   // ceil(NNODE*32/256)
#define EDGE_BLKS 5860   // ceil(EE/256)

// fp16 weight buffer offsets (halves), transposed [n][K] per matrix
#define OFF_U  0
#define OFF_I  40960
#define OFF_W0 81920
#define OFF_W1 114688
#define OFF_V0 147456
#define OFF_V1 163840
#define WTOT   180224

// smem strides (halves) — conflict-free for ldmatrix phases
#define PSTR 40   // proj tiles: 32 data + 8 pad
#define SSTR 24   // sage tiles: 16 data + 8 pad

// -------- scratch (device globals: allocation-free) --------
__device__ __half g_cat16[(size_t)NNODE * KCAT];
__device__ __half g_x16  [(size_t)NNODE * DD];
__device__ __half g_agg16[(size_t)NNODE * DD];
__device__ __half g_wth  [WTOT];
__device__ int    g_deg[NNODE];
__device__ int    g_bsum[1024];
__device__ int    g_offs[NNODE + 1];
__device__ int    g_cursor[NNODE];
__device__ int    g_csr[EE];
__device__ __nv_bfloat16 g_ufeb[5000 * 128];
__device__ __nv_bfloat16 g_ifeb[8000 * 128];
__device__ __nv_bfloat16 g_web [30000 * 64];

// -------- fp16 mma helper: m16n8k16, fp32 accumulate --------
__device__ __forceinline__ void mma_f16(float* c, const uint32_t* a, const uint32_t* b) {
    asm volatile(
        "mma.sync.aligned.m16n8k16.row.col.f32.f16.f16.f32 "
        "{%0,%1,%2,%3}, {%4,%5,%6,%7}, {%8,%9}, {%0,%1,%2,%3};"
        : "+f"(c[0]), "+f"(c[1]), "+f"(c[2]), "+f"(c[3])
        : "r"(a[0]), "r"(a[1]), "r"(a[2]), "r"(a[3]), "r"(b[0]), "r"(b[1]));
}

__device__ __forceinline__ void ldsm4(uint32_t* r, uint32_t addr) {
    asm volatile("ldmatrix.sync.aligned.m8n8.x4.shared.b16 {%0,%1,%2,%3}, [%4];"
                 : "=r"(r[0]), "=r"(r[1]), "=r"(r[2]), "=r"(r[3]) : "r"(addr));
}

__device__ __forceinline__ void cp16(void* smem_dst, const void* gsrc, bool pred) {
    uint32_t dst = (uint32_t)__cvta_generic_to_shared(smem_dst);
    int sz = pred ? 16 : 0;
    asm volatile("cp.async.ca.shared.global [%0], [%1], 16, %2;\n"
                 :: "r"(dst), "l"(gsrc), "r"(sz));
}
__device__ __forceinline__ void cp_commit() { asm volatile("cp.async.commit_group;\n"); }
__device__ __forceinline__ void cp_wait0()  { asm volatile("cp.async.wait_group 0;\n"); }
__device__ __forceinline__ void cp_wait1()  { asm volatile("cp.async.wait_group 1;\n"); }
__device__ __forceinline__ void cp_wait2()  { asm volatile("cp.async.wait_group 2;\n"); }
__device__ __forceinline__ void cp_wait3()  { asm volatile("cp.async.wait_group 3;\n"); }

// ======== prep: tables->bf16, weights->fp16 transposed [n][K], zero deg ========
__global__ void prep_kernel(const float* __restrict__ ufe, const float* __restrict__ ife,
                            const float* __restrict__ we,
                            const float* __restrict__ uW, const float* __restrict__ iW,
                            const float* __restrict__ w0, const float* __restrict__ w1,
                            const float* __restrict__ v0, const float* __restrict__ v1) {
    int i0 = blockIdx.x * blockDim.x + threadIdx.x;
    int st = gridDim.x * blockDim.x;
    for (int i = i0; i < 3584000; i += st) {
        if      (i < 640000)  g_ufeb[i]           = __float2bfloat16(ufe[i]);
        else if (i < 1664000) g_ifeb[i - 640000]  = __float2bfloat16(ife[i - 640000]);
        else                  g_web [i - 1664000] = __float2bfloat16(we [i - 1664000]);
    }
    for (int i = i0; i < WTOT; i += st) {
        const float* src; int loc, dbase, K;
        if      (i < OFF_I)  { src = uW; loc = i - OFF_U;  dbase = OFF_U;  K = 320; }
        else if (i < OFF_W0) { src = iW; loc = i - OFF_I;  dbase = OFF_I;  K = 320; }
        else if (i < OFF_W1) { src = w0; loc = i - OFF_W0; dbase = OFF_W0; K = 256; }
        else if (i < OFF_V0) { src = w1; loc = i - OFF_W1; dbase = OFF_W1; K = 256; }
        else if (i < OFF_V1) { src = v0; loc = i - OFF_V0; dbase = OFF_V0; K = 128; }
        else                 { src = v1; loc = i - OFF_V1; dbase = OFF_V1; K = 128; }
        int k = loc >> 7, n = loc & 127;
        g_wth[dbase + n * K + k] = __float2half(src[loc]);
    }
    for (int i = i0; i < NNODE; i += st) g_deg[i] = 0;
}

// ======== embed (fp16 output) + degree count ========
__global__ void embed_deg_kernel(const int* __restrict__ uf,  const int* __restrict__ itf,
                                 const int* __restrict__ ut,  const int* __restrict__ it,
                                 const int* __restrict__ dstp) {
    if (blockIdx.x >= EMB_BLKS) {
        int i = (blockIdx.x - EMB_BLKS) * blockDim.x + threadIdx.x;
        if (i < EE) atomicAdd(&g_deg[dstp[i]], 1);
        return;
    }
    int gw   = (blockIdx.x * blockDim.x + threadIdx.x) >> 5;
    int lane = threadIdx.x & 31;
    if (gw >= NNODE) return;
    int n = gw;
    bool user = n < NUSR;
    const int* f = user ? uf + (size_t)n * 10 : itf + (size_t)(n - NUSR) * 10;
    const __nv_bfloat16* tab = user ? g_ufeb : g_ifeb;

    float4 a = make_float4(0.f, 0.f, 0.f, 0.f);
#pragma unroll
    for (int j = 0; j < 10; j++) {
        int r = __ldg(f + j);
        uint2 v = __ldg((const uint2*)(tab + (size_t)r * DD) + lane);
        float2 p0 = __bfloat1622float2(*(__nv_bfloat162*)&v.x);
        float2 p1 = __bfloat1622float2(*(__nv_bfloat162*)&v.y);
        a.x += p0.x; a.y += p0.y; a.z += p1.x; a.w += p1.y;
    }
    __half* catrow = g_cat16 + (size_t)n * KCAT;
    __half2 h01 = __floats2half2_rn(a.x * 0.1f, a.y * 0.1f);
    __half2 h23 = __floats2half2_rn(a.z * 0.1f, a.w * 0.1f);
    uint2 pk;
    pk.x = *(uint32_t*)&h01; pk.y = *(uint32_t*)&h23;
    ((uint2*)catrow)[lane] = pk;

    const int* t = user ? ut + (size_t)n * 24 : it + (size_t)(n - NUSR) * 24;
#pragma unroll
    for (int fl = 0; fl < 3; fl++) {
        float2 b = make_float2(0.f, 0.f);
#pragma unroll
        for (int w = 0; w < 8; w++) {
            int r = __ldg(t + fl * 8 + w);
            uint32_t v = __ldg((const uint32_t*)(g_web + (size_t)r * HALFD) + lane);
            float2 p = __bfloat1622float2(*(__nv_bfloat162*)&v);
            b.x += p.x; b.y += p.y;
        }
        __half2 hb = __floats2half2_rn(b.x * 0.125f, b.y * 0.125f);
        *(uint32_t*)(catrow + 128 + fl * 64 + lane * 2) = *(uint32_t*)&hb;
    }
}

// -------- scans --------
__global__ void scan1_kernel() {
    __shared__ int sm[256];
    int tid = threadIdx.x;
    int i = blockIdx.x * 256 + tid;
    int v = (i < NNODE) ? g_deg[i] : 0;
    sm[tid] = v;
    __syncthreads();
#pragma unroll
    for (int d = 1; d < 256; d <<= 1) {
        int t = (tid >= d) ? sm[tid - d] : 0;
        __syncthreads();
        sm[tid] += t;
        __syncthreads();
    }
    if (i < NNODE) g_offs[i] = sm[tid] - v;
    if (tid == 255) g_bsum[blockIdx.x] = sm[255];
}

__global__ void scan2_kernel() {
    __shared__ int sm[1024];
    int tid = threadIdx.x;
    int v = (tid < NBLK) ? g_bsum[tid] : 0;
    sm[tid] = v;
    __syncthreads();
#pragma unroll
    for (int d = 1; d < 1024; d <<= 1) {
        int t = (tid >= d) ? sm[tid - d] : 0;
        __syncthreads();
        sm[tid] += t;
        __syncthreads();
    }
    g_bsum[tid] = sm[tid] - v;
}

__global__ void scan3_kernel() {
    int i = blockIdx.x * blockDim.x + threadIdx.x;
    if (i < NNODE) {
        int o = g_offs[i] + g_bsum[i >> 8];
        g_offs[i] = o;
        g_cursor[i] = o;
    }
    if (i == 0) g_offs[NNODE] = EE;
}

// -------- gather aggregation fp16, 4-way unrolled (warp per node) --------
__global__ void agg_kernel() {
    int gw   = (blockIdx.x * blockDim.x + threadIdx.x) >> 5;
    int lane = threadIdx.x & 31;
    if (gw >= NNODE) return;
    int off = g_offs[gw];
    int end = g_offs[gw + 1];
    float4 acc = make_float4(0.f, 0.f, 0.f, 0.f);
    int j = off;
    for (; j + 4 <= end; j += 4) {
        int s0 = __ldg(&g_csr[j]);
        int s1 = __ldg(&g_csr[j + 1]);
        int s2 = __ldg(&g_csr[j + 2]);
        int s3 = __ldg(&g_csr[j + 3]);
        uint2 v0 = __ldg((const uint2*)(g_x16 + (size_t)s0 * DD) + lane);
        uint2 v1 = __ldg((const uint2*)(g_x16 + (size_t)s1 * DD) + lane);
        uint2 v2 = __ldg((const uint2*)(g_x16 + (size_t)s2 * DD) + lane);
        uint2 v3 = __ldg((const uint2*)(g_x16 + (size_t)s3 * DD) + lane);
#pragma unroll
        for (int q = 0; q < 4; q++) {
            uint2 v = (q == 0) ? v0 : (q == 1) ? v1 : (q == 2) ? v2 : v3;
            float2 p0 = __half22float2(*(__half2*)&v.x);
            float2 p1 = __half22float2(*(__half2*)&v.y);
            acc.x += p0.x; acc.y += p0.y; acc.z += p1.x; acc.w += p1.y;
        }
    }
    for (; j < end; j++) {
        int s = __ldg(&g_csr[j]);
        uint2 v = __ldg((const uint2*)(g_x16 + (size_t)s * DD) + lane);
        float2 p0 = __half22float2(*(__half2*)&v.x);
        float2 p1 = __half22float2(*(__half2*)&v.y);
        acc.x += p0.x; acc.y += p0.y; acc.z += p1.x; acc.w += p1.y;
    }
    float sc = 1.0f / fmaxf((float)(end - off), 1.0f);
    __half2 p0 = __floats2half2_rn(acc.x * sc, acc.y * sc);
    __half2 p1 = __floats2half2_rn(acc.z * sc, acc.w * sc);
    uint2 pk;
    pk.x = *(uint32_t*)&p0; pk.y = *(uint32_t*)&p1;
    ((uint2*)(g_agg16 + (size_t)gw * DD))[lane] = pk;
}

// ======== fp16 projection GEMM (blocks [0,PROJ_BLKS)) + CSR fill (beyond) ========
__global__ __launch_bounds__(256) void proj_fill(
    const float* __restrict__ ubias, const float* __restrict__ ibias,
    const float* __restrict__ uid,   const float* __restrict__ iid,
    const int* __restrict__ srcp, const int* __restrict__ dstp)
{
    if (blockIdx.x >= PROJ_BLKS) {
        int i = (blockIdx.x - PROJ_BLKS) * blockDim.x + threadIdx.x;
        if (i < EE) {
            int d = dstp[i];
            int pos = atomicAdd(&g_cursor[d], 1);
            g_csr[pos] = srcp[i];
        }
        return;
    }

    extern __shared__ __half smh[];
    __half* As = smh;                       // 3*128*PSTR
    __half* Ws = smh + 3 * 128 * PSTR;      // 2*128*PSTR

    bool user = blockIdx.x < UBLKS;
    const __half* A      = user ? g_cat16 : g_cat16 + (size_t)NUSR * KCAT;
    const __half* Wt     = g_wth + (user ? OFF_U : OFF_I);
    const float* bias    = user ? ubias : ibias;
    const float* addmat  = user ? uid : iid;
    __half* out          = user ? g_x16 : g_x16 + (size_t)NUSR * DD;
    int M                = user ? NUSR : NITM;
    int r0               = (user ? blockIdx.x : blockIdx.x - UBLKS) * 128;

    int tid  = threadIdx.x;
    int lane = tid & 31;
    int wid  = tid >> 5;
    int wm = wid & 1, wn = wid >> 1;
    int g  = lane >> 2, tg = lane & 3;
    int lrow = (lane & 7) + ((lane & 8) ? 8 : 0);
    int lka  = (lane & 16) ? 8 : 0;
    int lnc  = (lane & 7) + ((lane & 16) ? 8 : 0);
    int lkb  = (lane & 8) ? 8 : 0;

    uint32_t as_sm = (uint32_t)__cvta_generic_to_shared(As);
    uint32_t ws_sm = (uint32_t)__cvta_generic_to_shared(Ws);

    float acc[4][4][4];
#pragma unroll
    for (int mt = 0; mt < 4; mt++)
#pragma unroll
        for (int nt = 0; nt < 4; nt++)
#pragma unroll
            for (int u = 0; u < 4; u++) acc[mt][nt][u] = 0.f;

    const int T = KCAT / 32;
    auto issueA = [&](int t, int s) {
#pragma unroll
        for (int l = 0; l < 2; l++) {
            int idx = tid + l * 256;
            int m = idx >> 2, c4 = idx & 3;
            int row = r0 + m;
            cp16(As + (size_t)s * 128 * PSTR + m * PSTR + c4 * 8,
                 A + (size_t)row * KCAT + t * 32 + c4 * 8, row < M);
        }
        cp_commit();
    };
    auto issueW = [&](int t, int s) {
#pragma unroll
        for (int l = 0; l < 2; l++) {
            int idx = tid + l * 256;
            int n = idx >> 2, c4 = idx & 3;
            cp16(Ws + (size_t)s * 128 * PSTR + n * PSTR + c4 * 8,
                 Wt + (size_t)n * KCAT + t * 32 + c4 * 8, true);
        }
        cp_commit();
    };

    issueW(0, 0);
    issueA(0, 0);
    issueA(1, 1);
    for (int t = 0; t < T; t++) {
        int sa = t % 3, sw = t & 1;
        if (t + 1 < T) issueW(t + 1, (t + 1) & 1);
        if (t + 2 < T) issueA(t + 2, (t + 2) % 3);
        if (t + 2 < T) cp_wait3();
        else if (t + 1 < T) cp_wait2();
        else cp_wait0();
        __syncthreads();
        uint32_t sab = as_sm + (uint32_t)sa * 128 * PSTR * 2;
        uint32_t swb = ws_sm + (uint32_t)sw * 128 * PSTR * 2;
#pragma unroll
        for (int kk = 0; kk < 32; kk += 16) {
            uint32_t afr[4][4];
#pragma unroll
            for (int mt = 0; mt < 4; mt++) {
                int rb0 = wm * 64 + mt * 16;
                ldsm4(afr[mt], sab + ((rb0 + lrow) * PSTR + kk + lka) * 2);
            }
            uint32_t bfr[4][2];
#pragma unroll
            for (int np = 0; np < 2; np++) {
                uint32_t r4[4];
                int nb0 = wn * 32 + np * 16;
                ldsm4(r4, swb + ((nb0 + lnc) * PSTR + kk + lkb) * 2);
                bfr[np * 2][0] = r4[0]; bfr[np * 2][1] = r4[1];
                bfr[np * 2 + 1][0] = r4[2]; bfr[np * 2 + 1][1] = r4[3];
            }
#pragma unroll
            for (int mt = 0; mt < 4; mt++)
#pragma unroll
                for (int nt = 0; nt < 4; nt++)
                    mma_f16(acc[mt][nt], afr[mt], bfr[nt]);
        }
        __syncthreads();
    }

#pragma unroll
    for (int mt = 0; mt < 4; mt++) {
#pragma unroll
        for (int nt = 0; nt < 4; nt++) {
            int col = wn * 32 + nt * 8 + tg * 2;
            int rowa = r0 + wm * 64 + mt * 16 + g;
            int rowb = rowa + 8;
            float b0 = bias[col], b1 = bias[col + 1];
            if (rowa < M) {
                float x0 = acc[mt][nt][0] + b0 + addmat[(size_t)rowa * 128 + col];
                float x1 = acc[mt][nt][1] + b1 + addmat[(size_t)rowa * 128 + col + 1];
                *(__half2*)(out + (size_t)rowa * 128 + col) = __floats2half2_rn(x0, x1);
            }
            if (rowb < M) {
                float x2 = acc[mt][nt][2] + b0 + addmat[(size_t)rowb * 128 + col];
                float x3 = acc[mt][nt][3] + b1 + addmat[(size_t)rowb * 128 + col + 1];
                *(__half2*)(out + (size_t)rowb * 128 + col) = __floats2half2_rn(x2, x3);
            }
        }
    }
}

// ======== fused SAGE layer fp16: 24 tiles BK=16, ldmatrix fragments ========
template <bool RELU, bool OUT16>
__global__ __launch_bounds__(256) void sage_layer(
    int voff, const float* __restrict__ vb,
    int woff, const float* __restrict__ wb,
    float* __restrict__ outf, int M)
{
    extern __shared__ __half smh[];
    __half*  As = smh;                           // 3*128*SSTR
    __half*  Ws = smh + 3 * 128 * SSTR;          // 2*128*SSTR
    __half2* H2 = (__half2*)(smh + 3 * 128 * SSTR + 2 * 128 * SSTR);
    const __half* vW = g_wth + voff;
    const __half* wW = g_wth + woff;

    int tid  = threadIdx.x;
    int lane = tid & 31;
    int wid  = tid >> 5;
    int wm = wid & 1, wn = wid >> 1;
    int g  = lane >> 2, tg = lane & 3;
    int lrow = (lane & 7) + ((lane & 8) ? 8 : 0);
    int lka  = (lane & 16) ? 8 : 0;
    int lnc  = (lane & 7) + ((lane & 16) ? 8 : 0);
    int lkb  = (lane & 8) ? 8 : 0;
    int r0 = blockIdx.x * 128;

    uint32_t as_sm = (uint32_t)__cvta_generic_to_shared(As);
    uint32_t ws_sm = (uint32_t)__cvta_generic_to_shared(Ws);
    uint32_t h2_sm = (uint32_t)__cvta_generic_to_shared(H2);

    float acc[4][4][4];
#pragma unroll
    for (int mt = 0; mt < 4; mt++)
#pragma unroll
        for (int nt = 0; nt < 4; nt++)
#pragma unroll
            for (int u = 0; u < 4; u++) acc[mt][nt][u] = 0.f;

    auto issueA = [&](int at, int s) {
        const __half* Ap = (at < 8) ? g_agg16 : g_x16;
        int kt = (at < 8) ? at : at - 8;
        int m = tid >> 1, c2 = tid & 1;
        int row = r0 + m;
        cp16(As + (size_t)s * 128 * SSTR + m * SSTR + c2 * 8,
             Ap + (size_t)row * DD + kt * 16 + c2 * 8, row < M);
        cp_commit();
    };
    auto issueW = [&](int wt, int s) {
        int n = tid >> 1, c2 = tid & 1;
        const __half* src = (wt < 8) ? (vW + (size_t)n * 128 + wt * 16)
                                     : (wW + (size_t)n * 256 + (wt - 8) * 16);
        cp16(Ws + (size_t)s * 128 * SSTR + n * SSTR + c2 * 8, src + c2 * 8, true);
        cp_commit();
    };

    issueW(0, 0);
    issueA(0, 0);
    issueA(1, 1);

    for (int t = 0; t < 24; t++) {
        int sa = t % 3, sw = t & 1;
        if (t + 1 < 24) issueW(t + 1, (t + 1) & 1);
        if (t + 2 < 16) issueA(t + 2, (t + 2) % 3);
        if (t < 14) cp_wait3();
        else if (t == 14) cp_wait2();
        else if (t < 23) cp_wait1();
        else cp_wait0();
        __syncthreads();

        uint32_t sab = as_sm + (uint32_t)sa * 128 * SSTR * 2;
        uint32_t swb = ws_sm + (uint32_t)sw * 128 * SSTR * 2;
        int hcp = (t - 16) * 8;
        {
            uint32_t afr[4][4];
#pragma unroll
            for (int mt = 0; mt < 4; mt++) {
                int rb0 = wm * 64 + mt * 16;
                if (t < 16) {
                    ldsm4(afr[mt], sab + ((rb0 + lrow) * SSTR + lka) * 2);
                } else {
                    int row = rb0 + lrow;
                    int xr = (row & 7) << 2;
                    int word = (hcp + (lka >> 1)) ^ xr;
                    ldsm4(afr[mt], h2_sm + (row * 64 + word) * 4);
                }
            }
            uint32_t bfr[4][2];
#pragma unroll
            for (int np = 0; np < 2; np++) {
                uint32_t r4[4];
                int nb0 = wn * 32 + np * 16;
                ldsm4(r4, swb + ((nb0 + lnc) * SSTR + lkb) * 2);
                bfr[np * 2][0] = r4[0]; bfr[np * 2][1] = r4[1];
                bfr[np * 2 + 1][0] = r4[2]; bfr[np * 2 + 1][1] = r4[3];
            }
#pragma unroll
            for (int mt = 0; mt < 4; mt++)
#pragma unroll
                for (int nt = 0; nt < 4; nt++)
                    mma_f16(acc[mt][nt], afr[mt], bfr[nt]);
        }

        if (t == 7) {
#pragma unroll
            for (int mt = 0; mt < 4; mt++) {
#pragma unroll
                for (int nt = 0; nt < 4; nt++) {
                    int col = wn * 32 + nt * 8 + tg * 2;
                    int ra = wm * 64 + mt * 16 + g;
                    int cp = col >> 1;
                    float b0 = vb[col], b1 = vb[col + 1];
                    int xra = (ra & 7) << 2;
                    H2[ra * 64 + (cp ^ xra)] =
                        __floats2half2_rn(fmaxf(acc[mt][nt][0] + b0, 0.f),
                                          fmaxf(acc[mt][nt][1] + b1, 0.f));
                    int xrb = ((ra + 8) & 7) << 2;
                    H2[(ra + 8) * 64 + (cp ^ xrb)] =
                        __floats2half2_rn(fmaxf(acc[mt][nt][2] + b0, 0.f),
                                          fmaxf(acc[mt][nt][3] + b1, 0.f));
#pragma unroll
                    for (int u = 0; u < 4; u++) acc[mt][nt][u] = 0.f;
                }
            }
        }
        __syncthreads();
    }

    // epilogue
#pragma unroll
    for (int mt = 0; mt < 4; mt++) {
#pragma unroll
        for (int nt = 0; nt < 4; nt++) {
            int col = wn * 32 + nt * 8 + tg * 2;
            int rowa = r0 + wm * 64 + mt * 16 + g;
            int rowb = rowa + 8;
            float b0 = wb[col], b1 = wb[col + 1];
            float x0 = acc[mt][nt][0] + b0, x1 = acc[mt][nt][1] + b1;
            float x2 = acc[mt][nt][2] + b0, x3 = acc[mt][nt][3] + b1;
            if (RELU) {
                x0 = fmaxf(x0, 0.f); x1 = fmaxf(x1, 0.f);
                x2 = fmaxf(x2, 0.f); x3 = fmaxf(x3, 0.f);
            }
            if (OUT16) {
                if (rowa < M)
                    *(__half2*)(g_x16 + (size_t)rowa * 128 + col) = __floats2half2_rn(x0, x1);
                if (rowb < M)
                    *(__half2*)(g_x16 + (size_t)rowb * 128 + col) = __floats2half2_rn(x2, x3);
            } else {
                if (rowa < M)
                    *(float2*)(outf + (size_t)rowa * 128 + col) = make_float2(x0, x1);
                if (rowb < M)
                    *(float2*)(outf + (size_t)rowb * 128 + col) = make_float2(x2, x3);
            }
        }
    }
}

// -------- launch --------
extern "C" void kernel_launch(void* const* d_in, const int* in_sizes, int n_in,
                              void* d_out, int out_size) {
    const int*   edge          = (const int*)d_in[0];
    const int*   src           = edge;
    const int*   dstp          = edge + EE;
    const int*   user_features = (const int*)d_in[1];
    const int*   item_features = (const int*)d_in[2];
    const int*   user_text     = (const int*)d_in[3];
    const int*   item_text     = (const int*)d_in[4];
    const float* user_id_emb   = (const float*)d_in[5];
    const float* item_id_emb   = (const float*)d_in[6];
    const float* user_feat_emb = (const float*)d_in[7];
    const float* item_feat_emb = (const float*)d_in[8];
    const float* word_emb      = (const float*)d_in[9];
    const float* user_projW    = (const float*)d_in[10];
    const float* user_projb    = (const float*)d_in[11];
    const float* item_projW    = (const float*)d_in[12];
    const float* item_projb    = (const float*)d_in[13];
    const float* w0W = (const float*)d_in[14];
    const float* w0b = (const float*)d_in[15];
    const float* w1W = (const float*)d_in[16];
    const float* w1b = (const float*)d_in[17];
    const float* v0W = (const float*)d_in[18];
    const float* v0b = (const float*)d_in[19];
    const float* v1W = (const float*)d_in[20];
    const float* v1b = (const float*)d_in[21];

    const int PROJ_SMEM = (3 * 128 * PSTR + 2 * 128 * PSTR) * 2;                 // 51200
    const int SAGE_SMEM = (3 * 128 * SSTR + 2 * 128 * SSTR) * 2 + 128 * 128 * 2; // 63488
    cudaFuncSetAttribute(proj_fill, cudaFuncAttributeMaxDynamicSharedMemorySize, PROJ_SMEM);
    cudaFuncSetAttribute(sage_layer<true, true>,   cudaFuncAttributeMaxDynamicSharedMemorySize, SAGE_SMEM);
    cudaFuncSetAttribute(sage_layer<false, false>, cudaFuncAttributeMaxDynamicSharedMemorySize, SAGE_SMEM);

    // 0: tables->bf16, weights->fp16^T, zero deg
    prep_kernel<<<2048, 256>>>(user_feat_emb, item_feat_emb, word_emb,
                               user_projW, item_projW, w0W, w1W, v0W, v1W);
    // 1: embed fp16 (+ deg counting riding along)
    embed_deg_kernel<<<EMB_BLKS + EDGE_BLKS, 256>>>(
        user_features, item_features, user_text, item_text, dstp);
    // 2-4: exclusive scan of degrees
    scan1_kernel<<<NBLK, 256>>>();
    scan2_kernel<<<1, 1024>>>();
    scan3_kernel<<<(NNODE + 255) / 256, 256>>>();
    // 5: fp16 projection GEMM (+ CSR fill riding along) -> g_x16
    proj_fill<<<PROJ_BLKS + EDGE_BLKS, 256, PROJ_SMEM>>>(
        user_projb, item_projb, user_id_emb, item_id_emb, src, dstp);

    // ----- layer 0 -----
    agg_kernel<<<(NNODE * 32 + 255) / 256, 256>>>();
    sage_layer<true, true><<<(NNODE + 127) / 128, 256, SAGE_SMEM>>>(
        OFF_V0, v0b, OFF_W0, w0b, nullptr, NNODE);

    // ----- layer 1 -----
    agg_kernel<<<(NNODE * 32 + 255) / 256, 256>>>();
    sage_layer<false, false><<<(NNODE + 127) / 128, 256, SAGE_SMEM>>>(
        OFF_V1, v1b, OFF_W1, w1b, (float*)d_out, NNODE);
}